// round 15
// baseline (speedup 1.0000x reference)
#include <cuda_runtime.h>
#include <cuda_bf16.h>
#include <cstdint>

#define NN 50000
#define EE 640000
#define HH 128

// ============================ device scratch ============================
__device__ __align__(16) float g_Amat[NN * HH];
__device__ __align__(16) float g_Bmat[NN * HH];
__device__ __align__(16) float g_yz[NN];          // z . W_dec[0:128] per node
__device__ int   g_counts[NN];
__device__ int   g_offsets[NN + 1];
__device__ int   g_cursor[NN];
__device__ __align__(16) int2 g_sedge[EE];
__device__ float g_hsum[HH];
__device__ int   g_done;
// pre-split bf16 activations (hi/lo)
__device__ __align__(16) __nv_bfloat16 g_ph_h[NN * HH], g_ph_l[NN * HH];
__device__ __align__(16) __nv_bfloat16 g_z_h[NN * HH],  g_z_l[NN * HH];
__device__ __align__(16) __nv_bfloat16 g_ag_h[NN * HH], g_ag_l[NN * HH];
// pre-split, pre-transposed weights: [n][k] bf16
__device__ __align__(16) __nv_bfloat16 g_Wenc_h[128 * 128], g_Wenc_l[128 * 128];
__device__ __align__(16) __nv_bfloat16 g_Wmsg_h[256 * 128], g_Wmsg_l[256 * 128];
__device__ __align__(16) __nv_bfloat16 g_Wupd_h[128 * 256], g_Wupd_l[128 * 256];

// ============================ helpers ============================
__device__ __forceinline__ uint32_t smem_u32(const void* p) {
    uint32_t a;
    asm("{ .reg .u64 t; cvta.to.shared.u64 t, %1; cvt.u32.u64 %0, t; }" : "=r"(a) : "l"(p));
    return a;
}
__device__ __forceinline__ void ldm_x4(uint32_t* d, uint32_t addr) {
    asm volatile("ldmatrix.sync.aligned.m8n8.x4.shared.b16 {%0,%1,%2,%3}, [%4];"
                 : "=r"(d[0]), "=r"(d[1]), "=r"(d[2]), "=r"(d[3]) : "r"(addr));
}
__device__ __forceinline__ void mma_bf16(float* c, const uint32_t* a, const uint32_t* b) {
    asm volatile(
        "mma.sync.aligned.m16n8k16.row.col.f32.bf16.bf16.f32 "
        "{%0,%1,%2,%3}, {%4,%5,%6,%7}, {%8,%9}, {%0,%1,%2,%3};"
        : "+f"(c[0]), "+f"(c[1]), "+f"(c[2]), "+f"(c[3])
        : "r"(a[0]), "r"(a[1]), "r"(a[2]), "r"(a[3]), "r"(b[0]), "r"(b[1]));
}
#define CP16(d, s, sz) asm volatile("cp.async.cg.shared.global [%0], [%1], 16, %2;" \
                                    :: "r"(d), "l"(s), "r"(sz) : "memory")
#define CP_COMMIT() asm volatile("cp.async.commit_group;" ::: "memory")
#define CP_WAIT0()  asm volatile("cp.async.wait_group 0;" ::: "memory")

__device__ __forceinline__ uint32_t pack_hi(float a, float b) {
    __nv_bfloat16 ha = __float2bfloat16(a), hb = __float2bfloat16(b);
    return (uint32_t)__bfloat16_as_ushort(ha) | ((uint32_t)__bfloat16_as_ushort(hb) << 16);
}
__device__ __forceinline__ uint32_t pack_lo(float a, float b) {
    __nv_bfloat16 ha = __float2bfloat16(a), hb = __float2bfloat16(b);
    float ra = a - __bfloat162float(ha), rb = b - __bfloat162float(hb);
    __nv_bfloat16 la = __float2bfloat16(ra), lb = __float2bfloat16(rb);
    return (uint32_t)__bfloat16_as_ushort(la) | ((uint32_t)__bfloat16_as_ushort(lb) << 16);
}

// ============================ init ============================
__global__ void init_kernel() {
    int i = blockIdx.x * blockDim.x + threadIdx.x;
    if (i < NN) g_counts[i] = 0;
    if (i < HH) g_hsum[i] = 0.f;
    if (i == HH) g_done = 0;
}

// ============================ weight prep ============================
__device__ __forceinline__ void split_store(float v, __nv_bfloat16* ph, __nv_bfloat16* pl, int idx) {
    __nv_bfloat16 h = __float2bfloat16(v);
    ph[idx] = h;
    pl[idx] = __float2bfloat16(v - __bfloat162float(h));
}
__global__ void prep_w_kernel(const float* __restrict__ W_enc,
                              const float* __restrict__ W_M,
                              const float* __restrict__ W_U) {
    int i = blockIdx.x * blockDim.x + threadIdx.x;
    if (i < 16384) {
        int n = i >> 7, k = i & 127;
        split_store(W_enc[(1 + k) * 128 + n], g_Wenc_h, g_Wenc_l, n * 128 + k);
    } else if (i < 49152) {
        int j = i - 16384;
        int n = j >> 7, k = j & 127;
        float v = (n < 128) ? W_M[k * 128 + n] : W_M[(128 + k) * 128 + (n - 128)];
        split_store(v, g_Wmsg_h, g_Wmsg_l, n * 128 + k);
    } else if (i < 81920) {
        int j = i - 49152;
        int n = j >> 8, k = j & 255;
        split_store(W_U[k * 128 + n], g_Wupd_h, g_Wupd_l, n * 256 + k);
    }
}

// ============================ activation pre-split ============================
__global__ void prep_x_kernel(const float* __restrict__ X,
                              __nv_bfloat16* __restrict__ Xh,
                              __nv_bfloat16* __restrict__ Xl, int npairs) {
    int i = blockIdx.x * blockDim.x + threadIdx.x;
    if (i < npairs) {
        float2 v = ((const float2*)X)[i];
        ((uint32_t*)Xh)[i] = pack_hi(v.x, v.y);
        ((uint32_t*)Xl)[i] = pack_lo(v.x, v.y);
    }
}

// ============================ mma.sync bf16 split GEMM ============================
// CTA tile 64(M) x 64(N), 8 warps as 2M x 4N. 3 CTAs/SM (smem 64KB). NB loop reuses X.
// Optional fused row-dot: when ydW != null, accumulates sum_col(out*ydW[col]) per row -> yz_out.
#define SM_XH 0
#define SM_XL 16384
#define SM_WH 32768
#define SM_WL 49152
#define SM_TOTAL 65536

__global__ __launch_bounds__(256, 3)
void gemm_mma(const __nv_bfloat16* __restrict__ X0h, const __nv_bfloat16* __restrict__ X0l,
              const __nv_bfloat16* __restrict__ X1h, const __nv_bfloat16* __restrict__ X1l,
              int nchunks,
              const __nv_bfloat16* __restrict__ Wh, const __nv_bfloat16* __restrict__ Wl,
              int Kw, int NB,
              const float* __restrict__ bias0, const float* __restrict__ bias1,
              const float* __restrict__ xcol, const float* __restrict__ w0,
              float* __restrict__ C0, float* __restrict__ C1,
              __nv_bfloat16* __restrict__ Sh, __nv_bfloat16* __restrict__ Sl,
              const float* __restrict__ ydW, float* __restrict__ yz_out,
              int M, int doRelu)
{
    extern __shared__ char smem[];
    __shared__ float ypart[64];
    const uint32_t sb = smem_u32(smem);
    const int tid  = threadIdx.x;
    const int warp = tid >> 5;
    const int lane = tid & 31;
    const int warp_m = warp >> 2;
    const int warp_n = warp & 3;
    const int row0 = blockIdx.x * 64;

    if (ydW && tid < 64) ypart[tid] = 0.f;

    const int a_r = lane & 15;
    const int a_k1 = (lane & 16) ? 1 : 0;
    const int b_n = (lane & 7) + ((lane & 16) ? 8 : 0);
    const int b_k1 = (lane & 8) ? 1 : 0;

    float yacc[2][2] = {{0.f, 0.f}, {0.f, 0.f}};   // [mt][half]

    for (int nb = 0; nb < NB; nb++) {
        const int globalN = blockIdx.y * NB + nb;
        float acc[2][2][4];
#pragma unroll
        for (int mt = 0; mt < 2; mt++)
#pragma unroll
            for (int nt = 0; nt < 2; nt++)
#pragma unroll
                for (int j = 0; j < 4; j++) acc[mt][nt][j] = 0.f;

        for (int kc = 0; kc < nchunks; kc++) {
            const __nv_bfloat16* Xh = kc ? X1h : X0h;
            const __nv_bfloat16* Xl = kc ? X1l : X0l;
            if (nb == 0 || nchunks > 1) {
                for (int idx = tid; idx < 1024; idx += 256) {
                    int row = idx >> 4, c16 = idx & 15;
                    int grow = row0 + row;
                    int grc = (grow < M) ? grow : 0;
                    uint32_t sz = (grow < M) ? 16u : 0u;
                    uint32_t soff = (uint32_t)row * 256 + (uint32_t)((c16 ^ (row & 7)) << 4);
                    size_t go = (size_t)grc * 128 + (size_t)c16 * 8;
                    CP16(sb + SM_XH + soff, Xh + go, sz);
                    CP16(sb + SM_XL + soff, Xl + go, sz);
                }
            }
            for (int idx = tid; idx < 1024; idx += 256) {
                int n = idx >> 4, c16 = idx & 15;
                int gn = globalN * 64 + n;
                uint32_t soff = (uint32_t)n * 256 + (uint32_t)((c16 ^ (n & 7)) << 4);
                size_t go = (size_t)gn * Kw + (size_t)(kc << 7) + (size_t)c16 * 8;
                CP16(sb + SM_WH + soff, Wh + go, 16u);
                CP16(sb + SM_WL + soff, Wl + go, 16u);
            }
            CP_COMMIT();
            CP_WAIT0();
            __syncthreads();

#pragma unroll 2
            for (int ks = 0; ks < 8; ks++) {
                const int akc = ks * 2 + a_k1;
                const int bkc = ks * 2 + b_k1;
                uint32_t ah[2][4], al[2][4];
#pragma unroll
                for (int mt = 0; mt < 2; mt++) {
                    int r = warp_m * 32 + mt * 16 + a_r;
                    uint32_t addr = sb + SM_XH + (uint32_t)r * 256 + (uint32_t)((akc ^ (r & 7)) << 4);
                    ldm_x4(ah[mt], addr);
                    ldm_x4(al[mt], addr + (SM_XL - SM_XH));
                }
                uint32_t bh[2][2], bl[2][2];
                {
                    int n = warp_n * 16 + b_n;
                    uint32_t addr = sb + SM_WH + (uint32_t)n * 256 + (uint32_t)((bkc ^ (n & 7)) << 4);
                    uint32_t t[4];
                    ldm_x4(t, addr);
                    bh[0][0] = t[0]; bh[0][1] = t[1];
                    bh[1][0] = t[2]; bh[1][1] = t[3];
                    ldm_x4(t, addr + (SM_WL - SM_WH));
                    bl[0][0] = t[0]; bl[0][1] = t[1];
                    bl[1][0] = t[2]; bl[1][1] = t[3];
                }
#pragma unroll
                for (int mt = 0; mt < 2; mt++)
#pragma unroll
                    for (int nt = 0; nt < 2; nt++) {
                        mma_bf16(acc[mt][nt], ah[mt], bh[nt]);
                        mma_bf16(acc[mt][nt], ah[mt], bl[nt]);
                        mma_bf16(acc[mt][nt], al[mt], bh[nt]);
                    }
            }
            __syncthreads();
        }

        // ---- epilogue for this N tile ----
        const int halfIdx = globalN >> 1;
        const int colbase = (globalN & 1) * 64;
        const float* bp = halfIdx ? bias1 : bias0;
        float*       Cp = halfIdx ? C1 : C0;
#pragma unroll
        for (int mt = 0; mt < 2; mt++) {
#pragma unroll
            for (int nt = 0; nt < 2; nt++) {
                int r   = row0 + warp_m * 32 + mt * 16 + (lane >> 2);
                int col = colbase + warp_n * 16 + nt * 8 + (lane & 3) * 2;
                float b0 = 0.f, b1 = 0.f, w00 = 0.f, w01 = 0.f;
                if (bp) { b0 = bp[col]; b1 = bp[col + 1]; }
                if (w0) { w00 = w0[col]; w01 = w0[col + 1]; }
#pragma unroll
                for (int half = 0; half < 2; half++) {
                    int rr = r + half * 8;
                    if (rr < M) {
                        float xv = xcol ? xcol[rr] : 0.f;
                        float o0 = fmaf(xv, w00, acc[mt][nt][half * 2 + 0] + b0);
                        float o1 = fmaf(xv, w01, acc[mt][nt][half * 2 + 1] + b1);
                        if (doRelu) { o0 = fmaxf(o0, 0.f); o1 = fmaxf(o1, 0.f); }
                        if (Cp) *(float2*)(Cp + (size_t)rr * 128 + col) = make_float2(o0, o1);
                        if (Sh) {
                            size_t so = (size_t)rr * 128 + col;
                            *(uint32_t*)(Sh + so) = pack_hi(o0, o1);
                            *(uint32_t*)(Sl + so) = pack_lo(o0, o1);
                        }
                        if (ydW)
                            yacc[mt][half] += o0 * ydW[col] + o1 * ydW[col + 1];
                    }
                }
            }
        }
    }

    // ---- fused row-dot reduce (enc only) ----
    if (ydW) {
#pragma unroll
        for (int mt = 0; mt < 2; mt++)
#pragma unroll
            for (int half = 0; half < 2; half++) {
                float v = yacc[mt][half];
                v += __shfl_xor_sync(0xFFFFFFFFu, v, 1);
                v += __shfl_xor_sync(0xFFFFFFFFu, v, 2);
                if ((lane & 3) == 0)
                    atomicAdd(&ypart[warp_m * 32 + mt * 16 + (lane >> 2) + half * 8], v);
            }
        __syncthreads();
        if (tid < 64 && row0 + tid < M)
            yz_out[row0 + tid] = ypart[tid];
    }
}

// ============================ CSR build ============================
__global__ void hist_kernel(const int* __restrict__ dst) {
    int e = blockIdx.x * blockDim.x + threadIdx.x;
    if (e < EE) atomicAdd(&g_counts[dst[e]], 1);
}

__global__ void scan_kernel() {
    __shared__ int part[1024];
    int t = threadIdx.x;
    const int CH = (NN + 1023) / 1024;
    int base = t * CH;
    int s = 0;
    for (int i = 0; i < CH; i++) { int idx = base + i; if (idx < NN) s += g_counts[idx]; }
    part[t] = s; __syncthreads();
    for (int off = 1; off < 1024; off <<= 1) {
        int v = (t >= off) ? part[t - off] : 0;
        __syncthreads();
        part[t] += v;
        __syncthreads();
    }
    int run = (t == 0) ? 0 : part[t - 1];
    for (int i = 0; i < CH; i++) {
        int idx = base + i;
        if (idx < NN) { g_offsets[idx] = run; g_cursor[idx] = run; run += g_counts[idx]; }
    }
    if (t == 0) g_offsets[NN] = part[1023];
}

__global__ void scatter_kernel(const int* __restrict__ src, const int* __restrict__ dst,
                               const float* __restrict__ attr) {
    int e = blockIdx.x * blockDim.x + threadIdx.x;
    if (e < EE) {
        int d = dst[e];
        int pos = atomicAdd(&g_cursor[d], 1);
        g_sedge[pos] = make_int2(src[e], __float_as_int(attr[e]));
    }
}

// ============================ per-node edge max (4-way unrolled gather) ============================
__global__ __launch_bounds__(256)
void agg_kernel(const float* __restrict__ W_M) {
    int node = blockIdx.x * 8 + (threadIdx.x >> 5);
    if (node >= NN) return;
    int lane = threadIdx.x & 31;
    int c = lane * 4;
    float4 w4 = *(const float4*)(W_M + 256 * HH + c);
    float4 rm = make_float4(-1e30f, -1e30f, -1e30f, -1e30f);
    int e0 = g_offsets[node], e1 = g_offsets[node + 1];

    int e = e0;
    for (; e + 3 < e1; e += 4) {
        int2 p0 = g_sedge[e];
        int2 p1 = g_sedge[e + 1];
        int2 p2 = g_sedge[e + 2];
        int2 p3 = g_sedge[e + 3];
        const float4 b0 = *(const float4*)(g_Bmat + (size_t)p0.x * HH + c);
        const float4 b1 = *(const float4*)(g_Bmat + (size_t)p1.x * HH + c);
        const float4 b2 = *(const float4*)(g_Bmat + (size_t)p2.x * HH + c);
        const float4 b3 = *(const float4*)(g_Bmat + (size_t)p3.x * HH + c);
        float a0 = __int_as_float(p0.y), a1 = __int_as_float(p1.y);
        float a2 = __int_as_float(p2.y), a3 = __int_as_float(p3.y);
        rm.x = fmaxf(rm.x, fmaf(a0, w4.x, b0.x));
        rm.y = fmaxf(rm.y, fmaf(a0, w4.y, b0.y));
        rm.z = fmaxf(rm.z, fmaf(a0, w4.z, b0.z));
        rm.w = fmaxf(rm.w, fmaf(a0, w4.w, b0.w));
        rm.x = fmaxf(rm.x, fmaf(a1, w4.x, b1.x));
        rm.y = fmaxf(rm.y, fmaf(a1, w4.y, b1.y));
        rm.z = fmaxf(rm.z, fmaf(a1, w4.z, b1.z));
        rm.w = fmaxf(rm.w, fmaf(a1, w4.w, b1.w));
        rm.x = fmaxf(rm.x, fmaf(a2, w4.x, b2.x));
        rm.y = fmaxf(rm.y, fmaf(a2, w4.y, b2.y));
        rm.z = fmaxf(rm.z, fmaf(a2, w4.z, b2.z));
        rm.w = fmaxf(rm.w, fmaf(a2, w4.w, b2.w));
        rm.x = fmaxf(rm.x, fmaf(a3, w4.x, b3.x));
        rm.y = fmaxf(rm.y, fmaf(a3, w4.y, b3.y));
        rm.z = fmaxf(rm.z, fmaf(a3, w4.z, b3.z));
        rm.w = fmaxf(rm.w, fmaf(a3, w4.w, b3.w));
    }
    for (; e < e1; e++) {
        int2 p = g_sedge[e];
        float a = __int_as_float(p.y);
        float4 b4 = *(const float4*)(g_Bmat + (size_t)p.x * HH + c);
        rm.x = fmaxf(rm.x, fmaf(a, w4.x, b4.x));
        rm.y = fmaxf(rm.y, fmaf(a, w4.y, b4.y));
        rm.z = fmaxf(rm.z, fmaf(a, w4.z, b4.z));
        rm.w = fmaxf(rm.w, fmaf(a, w4.w, b4.w));
    }

    float4 a4 = *(const float4*)(g_Amat + (size_t)node * HH + c);
    float4 o;
    o.x = fmaxf(a4.x + rm.x, 0.f);
    o.y = fmaxf(a4.y + rm.y, 0.f);
    o.z = fmaxf(a4.z + rm.z, 0.f);
    o.w = fmaxf(a4.w + rm.w, 0.f);
    size_t so = (size_t)node * HH + c;
    *(uint32_t*)(g_ag_h + so)     = pack_hi(o.x, o.y);
    *(uint32_t*)(g_ag_h + so + 2) = pack_hi(o.z, o.w);
    *(uint32_t*)(g_ag_l + so)     = pack_lo(o.x, o.y);
    *(uint32_t*)(g_ag_l + so + 2) = pack_lo(o.z, o.w);
}

// ============================ fused decoder y + h column sums + tau ============================
__global__ __launch_bounds__(256)
void yh_kernel(const float* __restrict__ h, const float* __restrict__ W_dec,
               const float* __restrict__ b_dec,
               const float* __restrict__ W_term, const float* __restrict__ b_term,
               float* __restrict__ y, float* __restrict__ tau) {
    int warp = threadIdx.x >> 5;
    int lane = threadIdx.x & 31;
    int c = lane * 4;
    float4 wh = *(const float4*)(W_dec + HH + c);
    float bd = b_dec[0];
    float4 cs = make_float4(0.f, 0.f, 0.f, 0.f);
    for (int node = blockIdx.x * 8 + warp; node < NN; node += gridDim.x * 8) {
        float4 h4 = *(const float4*)(h + (size_t)node * HH + c);
        cs.x += h4.x; cs.y += h4.y; cs.z += h4.z; cs.w += h4.w;
        float s = h4.x * wh.x + h4.y * wh.y + h4.z * wh.z + h4.w * wh.w;
#pragma unroll
        for (int o = 16; o; o >>= 1) s += __shfl_down_sync(0xFFFFFFFFu, s, o);
        if (lane == 0) y[node] = s + g_yz[node] + bd;
    }
    __shared__ float sm[8][128];
    __shared__ int isLast;
    *(float4*)&sm[warp][c] = cs;
    __syncthreads();
    if (threadIdx.x < 128) {
        int col = threadIdx.x;
        float s = 0.f;
#pragma unroll
        for (int w = 0; w < 8; w++) s += sm[w][col];
        atomicAdd(&g_hsum[col], s);
    }
    __threadfence();
    __syncthreads();
    if (threadIdx.x == 0) {
        int t = atomicAdd(&g_done, 1);
        isLast = (t == (int)gridDim.x - 1) ? 1 : 0;
    }
    __syncthreads();
    if (isLast) {
        __shared__ float red[128];
        if (threadIdx.x < 128) {
            int t = threadIdx.x;
            float hs = *((volatile float*)&g_hsum[t]);
            red[t] = hs * (1.0f / (float)NN) * (W_term[t] + W_term[t + HH]);
        }
        __syncthreads();
        for (int o = 64; o; o >>= 1) {
            if (threadIdx.x < o && threadIdx.x + o < 128) red[threadIdx.x] += red[threadIdx.x + o];
            __syncthreads();
        }
        if (threadIdx.x == 0) tau[0] = red[0] + b_term[0];
    }
}

// ============================ launch ============================
extern "C" void kernel_launch(void* const* d_in, const int* in_sizes, int n_in,
                              void* d_out, int out_size)
{
    const float* x         = (const float*)d_in[0];
    const float* pre_h     = (const float*)d_in[1];
    const int*   edge_idx  = (const int*)  d_in[2];
    const float* edge_attr = (const float*)d_in[3];
    const float* W_enc     = (const float*)d_in[4];
    const float* b_enc     = (const float*)d_in[5];
    const float* W_M       = (const float*)d_in[6];
    const float* b_M       = (const float*)d_in[7];
    const float* W_U       = (const float*)d_in[8];
    const float* b_U       = (const float*)d_in[9];
    const float* W_dec     = (const float*)d_in[10];
    const float* b_dec     = (const float*)d_in[11];
    const float* W_term    = (const float*)d_in[12];
    const float* b_term    = (const float*)d_in[13];

    float* out   = (float*)d_out;
    float* h_out = out;
    float* y_out = out + (size_t)NN * HH;
    float* tau_o = out + (size_t)NN * HH + NN;

    const int* src = edge_idx;
    const int* dst = edge_idx + EE;

    float* A_p;  cudaGetSymbolAddress((void**)&A_p,  g_Amat);
    float* B_p;  cudaGetSymbolAddress((void**)&B_p,  g_Bmat);
    float* yz_p; cudaGetSymbolAddress((void**)&yz_p, g_yz);
    __nv_bfloat16 *phh, *phl, *zh, *zl, *agh, *agl;
    cudaGetSymbolAddress((void**)&phh, g_ph_h);
    cudaGetSymbolAddress((void**)&phl, g_ph_l);
    cudaGetSymbolAddress((void**)&zh,  g_z_h);
    cudaGetSymbolAddress((void**)&zl,  g_z_l);
    cudaGetSymbolAddress((void**)&agh, g_ag_h);
    cudaGetSymbolAddress((void**)&agl, g_ag_l);
    __nv_bfloat16 *wench, *wencl, *wmsgh, *wmsgl, *wupdh, *wupdl;
    cudaGetSymbolAddress((void**)&wench, g_Wenc_h);
    cudaGetSymbolAddress((void**)&wencl, g_Wenc_l);
    cudaGetSymbolAddress((void**)&wmsgh, g_Wmsg_h);
    cudaGetSymbolAddress((void**)&wmsgl, g_Wmsg_l);
    cudaGetSymbolAddress((void**)&wupdh, g_Wupd_h);
    cudaGetSymbolAddress((void**)&wupdl, g_Wupd_l);

    cudaFuncSetAttribute(gemm_mma, cudaFuncAttributeMaxDynamicSharedMemorySize, SM_TOTAL);

    cudaStream_t s1;
    cudaStreamCreateWithFlags(&s1, cudaStreamNonBlocking);
    cudaEvent_t evA, evB;
    cudaEventCreateWithFlags(&evA, cudaEventDisableTiming);
    cudaEventCreateWithFlags(&evB, cudaEventDisableTiming);

    const int gemmGridX = (NN + 63) / 64;     // 782
    const int eBlocks   = (EE + 255) / 256;
    const int nWarpBlocks = (NN + 7) / 8;

    // 0) init (zeroes g_counts, g_hsum, g_done) — R9 topology
    init_kernel<<<(NN + 255) / 256, 256>>>();
    cudaEventRecord(evA, 0);

    // ---- branch s1: CSR build ----
    cudaStreamWaitEvent(s1, evA, 0);
    hist_kernel<<<eBlocks, 256, 0, s1>>>(dst);
    scan_kernel<<<1, 1024, 0, s1>>>();
    scatter_kernel<<<eBlocks, 256, 0, s1>>>(src, dst, edge_attr);
    cudaEventRecord(evB, s1);

    // ---- main chain: prep ----
    prep_w_kernel<<<320, 256>>>(W_enc, W_M, W_U);
    prep_x_kernel<<<(NN * 64 + 255) / 256, 256>>>(pre_h, phh, phl, NN * 64);

    // encoder: grid (782,1), NB=2; emits split z + fused yz row-dot (NO fp32 z store)
    gemm_mma<<<dim3(gemmGridX, 1), 256, SM_TOTAL>>>(
        phh, phl, nullptr, nullptr, 1, wench, wencl, 128, 2,
        b_enc, nullptr, x, W_enc,
        nullptr, nullptr, zh, zl, W_dec, yz_p, NN, 1);

    // fused msg: grid (782,2), NB=2
    gemm_mma<<<dim3(gemmGridX, 2), 256, SM_TOTAL>>>(
        zh, zl, nullptr, nullptr, 1, wmsgh, wmsgl, 128, 2,
        b_M, nullptr, nullptr, nullptr,
        A_p, B_p, nullptr, nullptr, nullptr, nullptr, NN, 0);

    // ---- join CSR, aggregate ----
    cudaStreamWaitEvent(0, evB, 0);
    agg_kernel<<<nWarpBlocks, 256>>>(W_M);

    // update: grid (782,2), NB=1, K=2 chunks
    gemm_mma<<<dim3(gemmGridX, 2), 256, SM_TOTAL>>>(
        zh, zl, agh, agl, 2, wupdh, wupdl, 256, 1,
        b_U, nullptr, nullptr, nullptr,
        h_out, nullptr, nullptr, nullptr, nullptr, nullptr, NN, 1);

    // ---- fused decoder + column sums + tau ----
    yh_kernel<<<384, 256>>>(h_out, W_dec, b_dec, W_term, b_term, y_out, tau_o);
}

// round 16
// speedup vs baseline: 1.0118x; 1.0118x over previous
#include <cuda_runtime.h>
#include <cuda_bf16.h>
#include <cuda_fp16.h>
#include <cstdint>

#define NN 50000
#define EE 640000
#define HH 128

// ============================ device scratch ============================
__device__ __align__(16) float g_z[NN * HH];
__device__ __align__(16) float g_Amat[NN * HH];
__device__ __align__(16) __half g_B16[NN * HH];   // msg B half (fp16 for half-traffic gather)
__device__ int   g_counts[NN];
__device__ int   g_offsets[NN + 1];
__device__ int   g_cursor[NN];
__device__ __align__(16) int2 g_sedge[EE];
__device__ float g_hsum[HH];
__device__ int   g_done;
// pre-split bf16 activations (hi/lo)
__device__ __align__(16) __nv_bfloat16 g_ph_h[NN * HH], g_ph_l[NN * HH];
__device__ __align__(16) __nv_bfloat16 g_z_h[NN * HH],  g_z_l[NN * HH];
__device__ __align__(16) __nv_bfloat16 g_ag_h[NN * HH], g_ag_l[NN * HH];
// pre-split, pre-transposed weights: [n][k] bf16
__device__ __align__(16) __nv_bfloat16 g_Wenc_h[128 * 128], g_Wenc_l[128 * 128];
__device__ __align__(16) __nv_bfloat16 g_Wmsg_h[256 * 128], g_Wmsg_l[256 * 128];
__device__ __align__(16) __nv_bfloat16 g_Wupd_h[128 * 256], g_Wupd_l[128 * 256];

// ============================ helpers ============================
__device__ __forceinline__ uint32_t smem_u32(const void* p) {
    uint32_t a;
    asm("{ .reg .u64 t; cvta.to.shared.u64 t, %1; cvt.u32.u64 %0, t; }" : "=r"(a) : "l"(p));
    return a;
}
__device__ __forceinline__ void ldm_x4(uint32_t* d, uint32_t addr) {
    asm volatile("ldmatrix.sync.aligned.m8n8.x4.shared.b16 {%0,%1,%2,%3}, [%4];"
                 : "=r"(d[0]), "=r"(d[1]), "=r"(d[2]), "=r"(d[3]) : "r"(addr));
}
__device__ __forceinline__ void mma_bf16(float* c, const uint32_t* a, const uint32_t* b) {
    asm volatile(
        "mma.sync.aligned.m16n8k16.row.col.f32.bf16.bf16.f32 "
        "{%0,%1,%2,%3}, {%4,%5,%6,%7}, {%8,%9}, {%0,%1,%2,%3};"
        : "+f"(c[0]), "+f"(c[1]), "+f"(c[2]), "+f"(c[3])
        : "r"(a[0]), "r"(a[1]), "r"(a[2]), "r"(a[3]), "r"(b[0]), "r"(b[1]));
}
#define CP16(d, s, sz) asm volatile("cp.async.cg.shared.global [%0], [%1], 16, %2;" \
                                    :: "r"(d), "l"(s), "r"(sz) : "memory")
#define CP_COMMIT() asm volatile("cp.async.commit_group;" ::: "memory")
#define CP_WAIT0()  asm volatile("cp.async.wait_group 0;" ::: "memory")

__device__ __forceinline__ uint32_t pack_hi(float a, float b) {
    __nv_bfloat16 ha = __float2bfloat16(a), hb = __float2bfloat16(b);
    return (uint32_t)__bfloat16_as_ushort(ha) | ((uint32_t)__bfloat16_as_ushort(hb) << 16);
}
__device__ __forceinline__ uint32_t pack_lo(float a, float b) {
    __nv_bfloat16 ha = __float2bfloat16(a), hb = __float2bfloat16(b);
    float ra = a - __bfloat162float(ha), rb = b - __bfloat162float(hb);
    __nv_bfloat16 la = __float2bfloat16(ra), lb = __float2bfloat16(rb);
    return (uint32_t)__bfloat16_as_ushort(la) | ((uint32_t)__bfloat16_as_ushort(lb) << 16);
}

// ============================ init ============================
__global__ void init_kernel() {
    int i = blockIdx.x * blockDim.x + threadIdx.x;
    if (i < NN) g_counts[i] = 0;
    if (i < HH) g_hsum[i] = 0.f;
    if (i == HH) g_done = 0;
}

// ============================ weight prep ============================
__device__ __forceinline__ void split_store(float v, __nv_bfloat16* ph, __nv_bfloat16* pl, int idx) {
    __nv_bfloat16 h = __float2bfloat16(v);
    ph[idx] = h;
    pl[idx] = __float2bfloat16(v - __bfloat162float(h));
}
__global__ void prep_w_kernel(const float* __restrict__ W_enc,
                              const float* __restrict__ W_M,
                              const float* __restrict__ W_U) {
    int i = blockIdx.x * blockDim.x + threadIdx.x;
    if (i < 16384) {
        int n = i >> 7, k = i & 127;
        split_store(W_enc[(1 + k) * 128 + n], g_Wenc_h, g_Wenc_l, n * 128 + k);
    } else if (i < 49152) {
        int j = i - 16384;
        int n = j >> 7, k = j & 127;
        float v = (n < 128) ? W_M[k * 128 + n] : W_M[(128 + k) * 128 + (n - 128)];
        split_store(v, g_Wmsg_h, g_Wmsg_l, n * 128 + k);
    } else if (i < 81920) {
        int j = i - 49152;
        int n = j >> 8, k = j & 255;
        split_store(W_U[k * 128 + n], g_Wupd_h, g_Wupd_l, n * 256 + k);
    }
}

// ============================ activation pre-split ============================
__global__ void prep_x_kernel(const float* __restrict__ X,
                              __nv_bfloat16* __restrict__ Xh,
                              __nv_bfloat16* __restrict__ Xl, int npairs) {
    int i = blockIdx.x * blockDim.x + threadIdx.x;
    if (i < npairs) {
        float2 v = ((const float2*)X)[i];
        ((uint32_t*)Xh)[i] = pack_hi(v.x, v.y);
        ((uint32_t*)Xl)[i] = pack_lo(v.x, v.y);
    }
}

// ============================ mma.sync bf16 split GEMM ============================
// CTA tile 64(M) x 64(N), 8 warps as 2M x 4N. 3 CTAs/SM (smem 64KB). NB loop reuses X.
// C1h16 != null: the halfIdx==1 output is stored as fp16 instead of fp32 C1.
#define SM_XH 0
#define SM_XL 16384
#define SM_WH 32768
#define SM_WL 49152
#define SM_TOTAL 65536

__global__ __launch_bounds__(256, 3)
void gemm_mma(const __nv_bfloat16* __restrict__ X0h, const __nv_bfloat16* __restrict__ X0l,
              const __nv_bfloat16* __restrict__ X1h, const __nv_bfloat16* __restrict__ X1l,
              int nchunks,
              const __nv_bfloat16* __restrict__ Wh, const __nv_bfloat16* __restrict__ Wl,
              int Kw, int NB,
              const float* __restrict__ bias0, const float* __restrict__ bias1,
              const float* __restrict__ xcol, const float* __restrict__ w0,
              float* __restrict__ C0, float* __restrict__ C1,
              __half* __restrict__ C1h16,
              __nv_bfloat16* __restrict__ Sh, __nv_bfloat16* __restrict__ Sl,
              int M, int doRelu)
{
    extern __shared__ char smem[];
    const uint32_t sb = smem_u32(smem);
    const int tid  = threadIdx.x;
    const int warp = tid >> 5;
    const int lane = tid & 31;
    const int warp_m = warp >> 2;
    const int warp_n = warp & 3;
    const int row0 = blockIdx.x * 64;

    const int a_r = lane & 15;
    const int a_k1 = (lane & 16) ? 1 : 0;
    const int b_n = (lane & 7) + ((lane & 16) ? 8 : 0);
    const int b_k1 = (lane & 8) ? 1 : 0;

    for (int nb = 0; nb < NB; nb++) {
        const int globalN = blockIdx.y * NB + nb;
        float acc[2][2][4];
#pragma unroll
        for (int mt = 0; mt < 2; mt++)
#pragma unroll
            for (int nt = 0; nt < 2; nt++)
#pragma unroll
                for (int j = 0; j < 4; j++) acc[mt][nt][j] = 0.f;

        for (int kc = 0; kc < nchunks; kc++) {
            const __nv_bfloat16* Xh = kc ? X1h : X0h;
            const __nv_bfloat16* Xl = kc ? X1l : X0l;
            if (nb == 0 || nchunks > 1) {
                for (int idx = tid; idx < 1024; idx += 256) {
                    int row = idx >> 4, c16 = idx & 15;
                    int grow = row0 + row;
                    int grc = (grow < M) ? grow : 0;
                    uint32_t sz = (grow < M) ? 16u : 0u;
                    uint32_t soff = (uint32_t)row * 256 + (uint32_t)((c16 ^ (row & 7)) << 4);
                    size_t go = (size_t)grc * 128 + (size_t)c16 * 8;
                    CP16(sb + SM_XH + soff, Xh + go, sz);
                    CP16(sb + SM_XL + soff, Xl + go, sz);
                }
            }
            for (int idx = tid; idx < 1024; idx += 256) {
                int n = idx >> 4, c16 = idx & 15;
                int gn = globalN * 64 + n;
                uint32_t soff = (uint32_t)n * 256 + (uint32_t)((c16 ^ (n & 7)) << 4);
                size_t go = (size_t)gn * Kw + (size_t)(kc << 7) + (size_t)c16 * 8;
                CP16(sb + SM_WH + soff, Wh + go, 16u);
                CP16(sb + SM_WL + soff, Wl + go, 16u);
            }
            CP_COMMIT();
            CP_WAIT0();
            __syncthreads();

#pragma unroll 2
            for (int ks = 0; ks < 8; ks++) {
                const int akc = ks * 2 + a_k1;
                const int bkc = ks * 2 + b_k1;
                uint32_t ah[2][4], al[2][4];
#pragma unroll
                for (int mt = 0; mt < 2; mt++) {
                    int r = warp_m * 32 + mt * 16 + a_r;
                    uint32_t addr = sb + SM_XH + (uint32_t)r * 256 + (uint32_t)((akc ^ (r & 7)) << 4);
                    ldm_x4(ah[mt], addr);
                    ldm_x4(al[mt], addr + (SM_XL - SM_XH));
                }
                uint32_t bh[2][2], bl[2][2];
                {
                    int n = warp_n * 16 + b_n;
                    uint32_t addr = sb + SM_WH + (uint32_t)n * 256 + (uint32_t)((bkc ^ (n & 7)) << 4);
                    uint32_t t[4];
                    ldm_x4(t, addr);
                    bh[0][0] = t[0]; bh[0][1] = t[1];
                    bh[1][0] = t[2]; bh[1][1] = t[3];
                    ldm_x4(t, addr + (SM_WL - SM_WH));
                    bl[0][0] = t[0]; bl[0][1] = t[1];
                    bl[1][0] = t[2]; bl[1][1] = t[3];
                }
#pragma unroll
                for (int mt = 0; mt < 2; mt++)
#pragma unroll
                    for (int nt = 0; nt < 2; nt++) {
                        mma_bf16(acc[mt][nt], ah[mt], bh[nt]);
                        mma_bf16(acc[mt][nt], ah[mt], bl[nt]);
                        mma_bf16(acc[mt][nt], al[mt], bh[nt]);
                    }
            }
            __syncthreads();
        }

        // ---- epilogue for this N tile ----
        const int halfIdx = globalN >> 1;
        const int colbase = (globalN & 1) * 64;
        const float* bp = halfIdx ? bias1 : bias0;
        float*       Cp = halfIdx ? C1 : C0;
        __half*      Hp = halfIdx ? C1h16 : nullptr;
#pragma unroll
        for (int mt = 0; mt < 2; mt++) {
#pragma unroll
            for (int nt = 0; nt < 2; nt++) {
                int r   = row0 + warp_m * 32 + mt * 16 + (lane >> 2);
                int col = colbase + warp_n * 16 + nt * 8 + (lane & 3) * 2;
                float b0 = 0.f, b1 = 0.f, w00 = 0.f, w01 = 0.f;
                if (bp) { b0 = bp[col]; b1 = bp[col + 1]; }
                if (w0) { w00 = w0[col]; w01 = w0[col + 1]; }
#pragma unroll
                for (int half = 0; half < 2; half++) {
                    int rr = r + half * 8;
                    if (rr < M) {
                        float xv = xcol ? xcol[rr] : 0.f;
                        float o0 = fmaf(xv, w00, acc[mt][nt][half * 2 + 0] + b0);
                        float o1 = fmaf(xv, w01, acc[mt][nt][half * 2 + 1] + b1);
                        if (doRelu) { o0 = fmaxf(o0, 0.f); o1 = fmaxf(o1, 0.f); }
                        if (Hp) {
                            *(__half2*)(Hp + (size_t)rr * 128 + col) = __floats2half2_rn(o0, o1);
                        } else if (Cp) {
                            *(float2*)(Cp + (size_t)rr * 128 + col) = make_float2(o0, o1);
                        }
                        if (Sh) {
                            size_t so = (size_t)rr * 128 + col;
                            *(uint32_t*)(Sh + so) = pack_hi(o0, o1);
                            *(uint32_t*)(Sl + so) = pack_lo(o0, o1);
                        }
                    }
                }
            }
        }
    }
}

// ============================ CSR build ============================
__global__ void hist_kernel(const int* __restrict__ dst) {
    int e = blockIdx.x * blockDim.x + threadIdx.x;
    if (e < EE) atomicAdd(&g_counts[dst[e]], 1);
}

__global__ void scan_kernel() {
    __shared__ int part[1024];
    int t = threadIdx.x;
    const int CH = (NN + 1023) / 1024;
    int base = t * CH;
    int s = 0;
    for (int i = 0; i < CH; i++) { int idx = base + i; if (idx < NN) s += g_counts[idx]; }
    part[t] = s; __syncthreads();
    for (int off = 1; off < 1024; off <<= 1) {
        int v = (t >= off) ? part[t - off] : 0;
        __syncthreads();
        part[t] += v;
        __syncthreads();
    }
    int run = (t == 0) ? 0 : part[t - 1];
    for (int i = 0; i < CH; i++) {
        int idx = base + i;
        if (idx < NN) { g_offsets[idx] = run; g_cursor[idx] = run; run += g_counts[idx]; }
    }
    if (t == 0) g_offsets[NN] = part[1023];
}

__global__ void scatter_kernel(const int* __restrict__ src, const int* __restrict__ dst,
                               const float* __restrict__ attr) {
    int e = blockIdx.x * blockDim.x + threadIdx.x;
    if (e < EE) {
        int d = dst[e];
        int pos = atomicAdd(&g_cursor[d], 1);
        g_sedge[pos] = make_int2(src[e], __float_as_int(attr[e]));
    }
}

// ============================ per-node edge max (fp16 gather, 4-way unroll) ============================
__device__ __forceinline__ void max_edge(float4& rm, float a, const float4& w4, uint2 raw) {
    float2 f01 = __half22float2(*(__half2*)&raw.x);
    float2 f23 = __half22float2(*(__half2*)&raw.y);
    rm.x = fmaxf(rm.x, fmaf(a, w4.x, f01.x));
    rm.y = fmaxf(rm.y, fmaf(a, w4.y, f01.y));
    rm.z = fmaxf(rm.z, fmaf(a, w4.z, f23.x));
    rm.w = fmaxf(rm.w, fmaf(a, w4.w, f23.y));
}

__global__ __launch_bounds__(256)
void agg_kernel(const float* __restrict__ W_M) {
    int node = blockIdx.x * 8 + (threadIdx.x >> 5);
    if (node >= NN) return;
    int lane = threadIdx.x & 31;
    int c = lane * 4;
    float4 w4 = *(const float4*)(W_M + 256 * HH + c);
    float4 rm = make_float4(-1e30f, -1e30f, -1e30f, -1e30f);
    int e0 = g_offsets[node], e1 = g_offsets[node + 1];

    int e = e0;
    for (; e + 3 < e1; e += 4) {
        int2 p0 = g_sedge[e];
        int2 p1 = g_sedge[e + 1];
        int2 p2 = g_sedge[e + 2];
        int2 p3 = g_sedge[e + 3];
        uint2 r0 = *(const uint2*)(g_B16 + (size_t)p0.x * HH + c);
        uint2 r1 = *(const uint2*)(g_B16 + (size_t)p1.x * HH + c);
        uint2 r2 = *(const uint2*)(g_B16 + (size_t)p2.x * HH + c);
        uint2 r3 = *(const uint2*)(g_B16 + (size_t)p3.x * HH + c);
        max_edge(rm, __int_as_float(p0.y), w4, r0);
        max_edge(rm, __int_as_float(p1.y), w4, r1);
        max_edge(rm, __int_as_float(p2.y), w4, r2);
        max_edge(rm, __int_as_float(p3.y), w4, r3);
    }
    for (; e < e1; e++) {
        int2 p = g_sedge[e];
        uint2 r = *(const uint2*)(g_B16 + (size_t)p.x * HH + c);
        max_edge(rm, __int_as_float(p.y), w4, r);
    }

    float4 a4 = *(const float4*)(g_Amat + (size_t)node * HH + c);
    float4 o;
    o.x = fmaxf(a4.x + rm.x, 0.f);
    o.y = fmaxf(a4.y + rm.y, 0.f);
    o.z = fmaxf(a4.z + rm.z, 0.f);
    o.w = fmaxf(a4.w + rm.w, 0.f);
    size_t so = (size_t)node * HH + c;
    *(uint32_t*)(g_ag_h + so)     = pack_hi(o.x, o.y);
    *(uint32_t*)(g_ag_h + so + 2) = pack_hi(o.z, o.w);
    *(uint32_t*)(g_ag_l + so)     = pack_lo(o.x, o.y);
    *(uint32_t*)(g_ag_l + so + 2) = pack_lo(o.z, o.w);
}

// ============================ fused decoder y + h column sums + tau ============================
__global__ __launch_bounds__(256)
void yh_kernel(const float* __restrict__ h, const float* __restrict__ W_dec,
               const float* __restrict__ b_dec,
               const float* __restrict__ W_term, const float* __restrict__ b_term,
               float* __restrict__ y, float* __restrict__ tau) {
    int warp = threadIdx.x >> 5;
    int lane = threadIdx.x & 31;
    int c = lane * 4;
    float4 wz = *(const float4*)(W_dec + c);
    float4 wh = *(const float4*)(W_dec + HH + c);
    float bd = b_dec[0];
    float4 cs = make_float4(0.f, 0.f, 0.f, 0.f);
    for (int node = blockIdx.x * 8 + warp; node < NN; node += gridDim.x * 8) {
        float4 z4 = *(const float4*)(g_z + (size_t)node * HH + c);
        float4 h4 = *(const float4*)(h + (size_t)node * HH + c);
        cs.x += h4.x; cs.y += h4.y; cs.z += h4.z; cs.w += h4.w;
        float s = z4.x * wz.x + z4.y * wz.y + z4.z * wz.z + z4.w * wz.w
                + h4.x * wh.x + h4.y * wh.y + h4.z * wh.z + h4.w * wh.w;
#pragma unroll
        for (int o = 16; o; o >>= 1) s += __shfl_down_sync(0xFFFFFFFFu, s, o);
        if (lane == 0) y[node] = s + bd;
    }
    __shared__ float sm[8][128];
    __shared__ int isLast;
    *(float4*)&sm[warp][c] = cs;
    __syncthreads();
    if (threadIdx.x < 128) {
        int col = threadIdx.x;
        float s = 0.f;
#pragma unroll
        for (int w = 0; w < 8; w++) s += sm[w][col];
        atomicAdd(&g_hsum[col], s);
    }
    __threadfence();
    __syncthreads();
    if (threadIdx.x == 0) {
        int t = atomicAdd(&g_done, 1);
        isLast = (t == (int)gridDim.x - 1) ? 1 : 0;
    }
    __syncthreads();
    if (isLast) {
        __shared__ float red[128];
        if (threadIdx.x < 128) {
            int t = threadIdx.x;
            float hs = *((volatile float*)&g_hsum[t]);
            red[t] = hs * (1.0f / (float)NN) * (W_term[t] + W_term[t + HH]);
        }
        __syncthreads();
        for (int o = 64; o; o >>= 1) {
            if (threadIdx.x < o && threadIdx.x + o < 128) red[threadIdx.x] += red[threadIdx.x + o];
            __syncthreads();
        }
        if (threadIdx.x == 0) tau[0] = red[0] + b_term[0];
    }
}

// ============================ launch ============================
extern "C" void kernel_launch(void* const* d_in, const int* in_sizes, int n_in,
                              void* d_out, int out_size)
{
    const float* x         = (const float*)d_in[0];
    const float* pre_h     = (const float*)d_in[1];
    const int*   edge_idx  = (const int*)  d_in[2];
    const float* edge_attr = (const float*)d_in[3];
    const float* W_enc     = (const float*)d_in[4];
    const float* b_enc     = (const float*)d_in[5];
    const float* W_M       = (const float*)d_in[6];
    const float* b_M       = (const float*)d_in[7];
    const float* W_U       = (const float*)d_in[8];
    const float* b_U       = (const float*)d_in[9];
    const float* W_dec     = (const float*)d_in[10];
    const float* b_dec     = (const float*)d_in[11];
    const float* W_term    = (const float*)d_in[12];
    const float* b_term    = (const float*)d_in[13];

    float* out   = (float*)d_out;
    float* h_out = out;
    float* y_out = out + (size_t)NN * HH;
    float* tau_o = out + (size_t)NN * HH + NN;

    const int* src = edge_idx;
    const int* dst = edge_idx + EE;

    float* z_p;  cudaGetSymbolAddress((void**)&z_p,  g_z);
    float* A_p;  cudaGetSymbolAddress((void**)&A_p,  g_Amat);
    __half* B16_p; cudaGetSymbolAddress((void**)&B16_p, g_B16);
    __nv_bfloat16 *phh, *phl, *zh, *zl, *agh, *agl;
    cudaGetSymbolAddress((void**)&phh, g_ph_h);
    cudaGetSymbolAddress((void**)&phl, g_ph_l);
    cudaGetSymbolAddress((void**)&zh,  g_z_h);
    cudaGetSymbolAddress((void**)&zl,  g_z_l);
    cudaGetSymbolAddress((void**)&agh, g_ag_h);
    cudaGetSymbolAddress((void**)&agl, g_ag_l);
    __nv_bfloat16 *wench, *wencl, *wmsgh, *wmsgl, *wupdh, *wupdl;
    cudaGetSymbolAddress((void**)&wench, g_Wenc_h);
    cudaGetSymbolAddress((void**)&wencl, g_Wenc_l);
    cudaGetSymbolAddress((void**)&wmsgh, g_Wmsg_h);
    cudaGetSymbolAddress((void**)&wmsgl, g_Wmsg_l);
    cudaGetSymbolAddress((void**)&wupdh, g_Wupd_h);
    cudaGetSymbolAddress((void**)&wupdl, g_Wupd_l);

    cudaFuncSetAttribute(gemm_mma, cudaFuncAttributeMaxDynamicSharedMemorySize, SM_TOTAL);

    cudaStream_t s1;
    cudaStreamCreateWithFlags(&s1, cudaStreamNonBlocking);
    cudaEvent_t evA, evB;
    cudaEventCreateWithFlags(&evA, cudaEventDisableTiming);
    cudaEventCreateWithFlags(&evB, cudaEventDisableTiming);

    const int gemmGridX = (NN + 63) / 64;     // 782
    const int eBlocks   = (EE + 255) / 256;
    const int nWarpBlocks = (NN + 7) / 8;

    // 0) init — R9 topology
    init_kernel<<<(NN + 255) / 256, 256>>>();
    cudaEventRecord(evA, 0);

    // ---- branch s1: CSR build ----
    cudaStreamWaitEvent(s1, evA, 0);
    hist_kernel<<<eBlocks, 256, 0, s1>>>(dst);
    scan_kernel<<<1, 1024, 0, s1>>>();
    scatter_kernel<<<eBlocks, 256, 0, s1>>>(src, dst, edge_attr);
    cudaEventRecord(evB, s1);

    // ---- main chain: prep ----
    prep_w_kernel<<<320, 256>>>(W_enc, W_M, W_U);
    prep_x_kernel<<<(NN * 64 + 255) / 256, 256>>>(pre_h, phh, phl, NN * 64);

    // encoder: grid (782,1), NB=2
    gemm_mma<<<dim3(gemmGridX, 1), 256, SM_TOTAL>>>(
        phh, phl, nullptr, nullptr, 1, wench, wencl, 128, 2,
        b_enc, nullptr, x, W_enc,
        z_p, nullptr, nullptr, zh, zl, NN, 1);

    // fused msg: grid (782,2), NB=2; A fp32, B fp16
    gemm_mma<<<dim3(gemmGridX, 2), 256, SM_TOTAL>>>(
        zh, zl, nullptr, nullptr, 1, wmsgh, wmsgl, 128, 2,
        b_M, nullptr, nullptr, nullptr,
        A_p, nullptr, B16_p, nullptr, nullptr, NN, 0);

    // ---- join CSR, aggregate ----
    cudaStreamWaitEvent(0, evB, 0);
    agg_kernel<<<nWarpBlocks, 256>>>(W_M);

    // update: grid (782,2), NB=1, K=2 chunks
    gemm_mma<<<dim3(gemmGridX, 2), 256, SM_TOTAL>>>(
        zh, zl, agh, agl, 2, wupdh, wupdl, 256, 1,
        b_U, nullptr, nullptr, nullptr,
        h_out, nullptr, nullptr, nullptr, nullptr, NN, 1);

    // ---- fused decoder + column sums + tau ----
    yh_kernel<<<384, 256>>>(h_out, W_dec, b_dec, W_term, b_term, y_out, tau_o);
}

// round 17
// speedup vs baseline: 1.0828x; 1.0701x over previous
#include <cuda_runtime.h>
#include <cuda_fp16.h>
#include <cstdint>

#define NN 50000
#define EE 640000
#define HH 128

// ============================ device scratch ============================
__device__ __align__(16) float g_z[NN * HH];      // fp32 z for yh decoder dot
__device__ __align__(16) float g_Amat[NN * HH];
__device__ __align__(16) __half g_B16[NN * HH];   // msg B half (fp16 gather)
__device__ int   g_counts[NN];
__device__ int   g_offsets[NN + 1];
__device__ int   g_cursor[NN];
__device__ __align__(16) int2 g_sedge[EE];
__device__ float g_hsum[HH];
__device__ int   g_done;
// fp16 activations
__device__ __align__(16) __half g_ph16[NN * HH];
__device__ __align__(16) __half g_z16[NN * HH];
__device__ __align__(16) __half g_ag16[NN * HH];
// split-fp16 weights: [n][k]
__device__ __align__(16) __half g_Wenc_h[128 * 128], g_Wenc_l[128 * 128];
__device__ __align__(16) __half g_Wmsg_h[256 * 128], g_Wmsg_l[256 * 128];
__device__ __align__(16) __half g_Wupd_h[128 * 256], g_Wupd_l[128 * 256];

// ============================ helpers ============================
__device__ __forceinline__ uint32_t smem_u32(const void* p) {
    uint32_t a;
    asm("{ .reg .u64 t; cvta.to.shared.u64 t, %1; cvt.u32.u64 %0, t; }" : "=r"(a) : "l"(p));
    return a;
}
__device__ __forceinline__ void ldm_x4(uint32_t* d, uint32_t addr) {
    asm volatile("ldmatrix.sync.aligned.m8n8.x4.shared.b16 {%0,%1,%2,%3}, [%4];"
                 : "=r"(d[0]), "=r"(d[1]), "=r"(d[2]), "=r"(d[3]) : "r"(addr));
}
__device__ __forceinline__ void mma_f16(float* c, const uint32_t* a, const uint32_t* b) {
    asm volatile(
        "mma.sync.aligned.m16n8k16.row.col.f32.f16.f16.f32 "
        "{%0,%1,%2,%3}, {%4,%5,%6,%7}, {%8,%9}, {%0,%1,%2,%3};"
        : "+f"(c[0]), "+f"(c[1]), "+f"(c[2]), "+f"(c[3])
        : "r"(a[0]), "r"(a[1]), "r"(a[2]), "r"(a[3]), "r"(b[0]), "r"(b[1]));
}
#define CP16(d, s, sz) asm volatile("cp.async.cg.shared.global [%0], [%1], 16, %2;" \
                                    :: "r"(d), "l"(s), "r"(sz) : "memory")
#define CP_COMMIT() asm volatile("cp.async.commit_group;" ::: "memory")
#define CP_WAIT0()  asm volatile("cp.async.wait_group 0;" ::: "memory")

// ============================ init ============================
__global__ void init_kernel() {
    int i = blockIdx.x * blockDim.x + threadIdx.x;
    if (i < NN) g_counts[i] = 0;
    if (i < HH) g_hsum[i] = 0.f;
    if (i == HH) g_done = 0;
}

// ============================ weight prep: transpose + fp16 split ============================
__device__ __forceinline__ void split_store16(float v, __half* ph, __half* pl, int idx) {
    __half h = __float2half_rn(v);
    ph[idx] = h;
    pl[idx] = __float2half_rn(v - __half2float(h));
}
__global__ void prep_w_kernel(const float* __restrict__ W_enc,
                              const float* __restrict__ W_M,
                              const float* __restrict__ W_U) {
    int i = blockIdx.x * blockDim.x + threadIdx.x;
    if (i < 16384) {
        int n = i >> 7, k = i & 127;
        split_store16(W_enc[(1 + k) * 128 + n], g_Wenc_h, g_Wenc_l, n * 128 + k);
    } else if (i < 49152) {
        int j = i - 16384;
        int n = j >> 7, k = j & 127;
        float v = (n < 128) ? W_M[k * 128 + n] : W_M[(128 + k) * 128 + (n - 128)];
        split_store16(v, g_Wmsg_h, g_Wmsg_l, n * 128 + k);
    } else if (i < 81920) {
        int j = i - 49152;
        int n = j >> 8, k = j & 255;
        split_store16(W_U[k * 128 + n], g_Wupd_h, g_Wupd_l, n * 256 + k);
    }
}

// ============================ activation fp16 convert ============================
__global__ void prep_x_kernel(const float* __restrict__ X,
                              __half* __restrict__ X16, int npairs) {
    int i = blockIdx.x * blockDim.x + threadIdx.x;
    if (i < npairs) {
        float2 v = ((const float2*)X)[i];
        ((__half2*)X16)[i] = __floats2half2_rn(v.x, v.y);
    }
}

// ============================ mma.sync fp16 GEMM (split-fp16 weights) ============================
// CTA tile 64(M) x 64(N), 8 warps as 2M x 4N. 4 CTAs/SM (smem 48KB). NB loop reuses X.
#define SM_X  0
#define SM_WH 16384
#define SM_WL 32768
#define SM_TOTAL 49152

__global__ __launch_bounds__(256, 4)
void gemm_mma(const __half* __restrict__ X0, const __half* __restrict__ X1,
              int nchunks,
              const __half* __restrict__ Wh, const __half* __restrict__ Wl,
              int Kw, int NB,
              const float* __restrict__ bias0, const float* __restrict__ bias1,
              const float* __restrict__ xcol, const float* __restrict__ w0,
              float* __restrict__ C0, float* __restrict__ C1,
              __half* __restrict__ C1h16,
              __half* __restrict__ S16,
              int M, int doRelu)
{
    extern __shared__ char smem[];
    const uint32_t sb = smem_u32(smem);
    const int tid  = threadIdx.x;
    const int warp = tid >> 5;
    const int lane = tid & 31;
    const int warp_m = warp >> 2;
    const int warp_n = warp & 3;
    const int row0 = blockIdx.x * 64;

    const int a_r = lane & 15;
    const int a_k1 = (lane & 16) ? 1 : 0;
    const int b_n = (lane & 7) + ((lane & 16) ? 8 : 0);
    const int b_k1 = (lane & 8) ? 1 : 0;

    for (int nb = 0; nb < NB; nb++) {
        const int globalN = blockIdx.y * NB + nb;
        float acc[2][2][4];
#pragma unroll
        for (int mt = 0; mt < 2; mt++)
#pragma unroll
            for (int nt = 0; nt < 2; nt++)
#pragma unroll
                for (int j = 0; j < 4; j++) acc[mt][nt][j] = 0.f;

        for (int kc = 0; kc < nchunks; kc++) {
            const __half* Xs = kc ? X1 : X0;
            // ---- X fill (64 rows x 128 k fp16 = 16 KB) ----
            if (nb == 0 || nchunks > 1) {
                for (int idx = tid; idx < 1024; idx += 256) {
                    int row = idx >> 4, c16 = idx & 15;
                    int grow = row0 + row;
                    int grc = (grow < M) ? grow : 0;
                    uint32_t sz = (grow < M) ? 16u : 0u;
                    uint32_t soff = (uint32_t)row * 256 + (uint32_t)((c16 ^ (row & 7)) << 4);
                    size_t go = (size_t)grc * 128 + (size_t)c16 * 8;
                    CP16(sb + SM_X + soff, Xs + go, sz);
                }
            }
            // ---- W fill (64 n x 128 k, hi+lo) ----
            for (int idx = tid; idx < 1024; idx += 256) {
                int n = idx >> 4, c16 = idx & 15;
                int gn = globalN * 64 + n;
                uint32_t soff = (uint32_t)n * 256 + (uint32_t)((c16 ^ (n & 7)) << 4);
                size_t go = (size_t)gn * Kw + (size_t)(kc << 7) + (size_t)c16 * 8;
                CP16(sb + SM_WH + soff, Wh + go, 16u);
                CP16(sb + SM_WL + soff, Wl + go, 16u);
            }
            CP_COMMIT();
            CP_WAIT0();
            __syncthreads();

#pragma unroll 2
            for (int ks = 0; ks < 8; ks++) {
                const int akc = ks * 2 + a_k1;
                const int bkc = ks * 2 + b_k1;
                uint32_t ah[2][4];
#pragma unroll
                for (int mt = 0; mt < 2; mt++) {
                    int r = warp_m * 32 + mt * 16 + a_r;
                    uint32_t addr = sb + SM_X + (uint32_t)r * 256 + (uint32_t)((akc ^ (r & 7)) << 4);
                    ldm_x4(ah[mt], addr);
                }
                uint32_t bh[2][2], bl[2][2];
                {
                    int n = warp_n * 16 + b_n;
                    uint32_t addr = sb + SM_WH + (uint32_t)n * 256 + (uint32_t)((bkc ^ (n & 7)) << 4);
                    uint32_t t[4];
                    ldm_x4(t, addr);
                    bh[0][0] = t[0]; bh[0][1] = t[1];
                    bh[1][0] = t[2]; bh[1][1] = t[3];
                    ldm_x4(t, addr + (SM_WL - SM_WH));
                    bl[0][0] = t[0]; bl[0][1] = t[1];
                    bl[1][0] = t[2]; bl[1][1] = t[3];
                }
#pragma unroll
                for (int mt = 0; mt < 2; mt++)
#pragma unroll
                    for (int nt = 0; nt < 2; nt++) {
                        mma_f16(acc[mt][nt], ah[mt], bh[nt]);
                        mma_f16(acc[mt][nt], ah[mt], bl[nt]);
                    }
            }
            __syncthreads();
        }

        // ---- epilogue for this N tile ----
        const int halfIdx = globalN >> 1;
        const int colbase = (globalN & 1) * 64;
        const float* bp = halfIdx ? bias1 : bias0;
        float*       Cp = halfIdx ? C1 : C0;
        __half*      Hp = halfIdx ? C1h16 : nullptr;
#pragma unroll
        for (int mt = 0; mt < 2; mt++) {
#pragma unroll
            for (int nt = 0; nt < 2; nt++) {
                int r   = row0 + warp_m * 32 + mt * 16 + (lane >> 2);
                int col = colbase + warp_n * 16 + nt * 8 + (lane & 3) * 2;
                float b0 = 0.f, b1 = 0.f, w00 = 0.f, w01 = 0.f;
                if (bp) { b0 = bp[col]; b1 = bp[col + 1]; }
                if (w0) { w00 = w0[col]; w01 = w0[col + 1]; }
#pragma unroll
                for (int half = 0; half < 2; half++) {
                    int rr = r + half * 8;
                    if (rr < M) {
                        float xv = xcol ? xcol[rr] : 0.f;
                        float o0 = fmaf(xv, w00, acc[mt][nt][half * 2 + 0] + b0);
                        float o1 = fmaf(xv, w01, acc[mt][nt][half * 2 + 1] + b1);
                        if (doRelu) { o0 = fmaxf(o0, 0.f); o1 = fmaxf(o1, 0.f); }
                        if (Hp) {
                            *(__half2*)(Hp + (size_t)rr * 128 + col) = __floats2half2_rn(o0, o1);
                        } else if (Cp) {
                            *(float2*)(Cp + (size_t)rr * 128 + col) = make_float2(o0, o1);
                        }
                        if (S16)
                            *(__half2*)(S16 + (size_t)rr * 128 + col) = __floats2half2_rn(o0, o1);
                    }
                }
            }
        }
    }
}

// ============================ CSR build ============================
__global__ void hist_kernel(const int* __restrict__ dst) {
    int e = blockIdx.x * blockDim.x + threadIdx.x;
    if (e < EE) atomicAdd(&g_counts[dst[e]], 1);
}

__global__ void scan_kernel() {
    __shared__ int part[1024];
    int t = threadIdx.x;
    const int CH = (NN + 1023) / 1024;
    int base = t * CH;
    int s = 0;
    for (int i = 0; i < CH; i++) { int idx = base + i; if (idx < NN) s += g_counts[idx]; }
    part[t] = s; __syncthreads();
    for (int off = 1; off < 1024; off <<= 1) {
        int v = (t >= off) ? part[t - off] : 0;
        __syncthreads();
        part[t] += v;
        __syncthreads();
    }
    int run = (t == 0) ? 0 : part[t - 1];
    for (int i = 0; i < CH; i++) {
        int idx = base + i;
        if (idx < NN) { g_offsets[idx] = run; g_cursor[idx] = run; run += g_counts[idx]; }
    }
    if (t == 0) g_offsets[NN] = part[1023];
}

__global__ void scatter_kernel(const int* __restrict__ src, const int* __restrict__ dst,
                               const float* __restrict__ attr) {
    int e = blockIdx.x * blockDim.x + threadIdx.x;
    if (e < EE) {
        int d = dst[e];
        int pos = atomicAdd(&g_cursor[d], 1);
        g_sedge[pos] = make_int2(src[e], __float_as_int(attr[e]));
    }
}

// ============================ per-node edge max (fp16 gather, 4-way unroll) ============================
__device__ __forceinline__ void max_edge(float4& rm, float a, const float4& w4, uint2 raw) {
    float2 f01 = __half22float2(*(__half2*)&raw.x);
    float2 f23 = __half22float2(*(__half2*)&raw.y);
    rm.x = fmaxf(rm.x, fmaf(a, w4.x, f01.x));
    rm.y = fmaxf(rm.y, fmaf(a, w4.y, f01.y));
    rm.z = fmaxf(rm.z, fmaf(a, w4.z, f23.x));
    rm.w = fmaxf(rm.w, fmaf(a, w4.w, f23.y));
}

__global__ __launch_bounds__(256)
void agg_kernel(const float* __restrict__ W_M) {
    int node = blockIdx.x * 8 + (threadIdx.x >> 5);
    if (node >= NN) return;
    int lane = threadIdx.x & 31;
    int c = lane * 4;
    float4 w4 = *(const float4*)(W_M + 256 * HH + c);
    float4 rm = make_float4(-1e30f, -1e30f, -1e30f, -1e30f);
    int e0 = g_offsets[node], e1 = g_offsets[node + 1];

    int e = e0;
    for (; e + 3 < e1; e += 4) {
        int2 p0 = g_sedge[e];
        int2 p1 = g_sedge[e + 1];
        int2 p2 = g_sedge[e + 2];
        int2 p3 = g_sedge[e + 3];
        uint2 r0 = *(const uint2*)(g_B16 + (size_t)p0.x * HH + c);
        uint2 r1 = *(const uint2*)(g_B16 + (size_t)p1.x * HH + c);
        uint2 r2 = *(const uint2*)(g_B16 + (size_t)p2.x * HH + c);
        uint2 r3 = *(const uint2*)(g_B16 + (size_t)p3.x * HH + c);
        max_edge(rm, __int_as_float(p0.y), w4, r0);
        max_edge(rm, __int_as_float(p1.y), w4, r1);
        max_edge(rm, __int_as_float(p2.y), w4, r2);
        max_edge(rm, __int_as_float(p3.y), w4, r3);
    }
    for (; e < e1; e++) {
        int2 p = g_sedge[e];
        uint2 r = *(const uint2*)(g_B16 + (size_t)p.x * HH + c);
        max_edge(rm, __int_as_float(p.y), w4, r);
    }

    float4 a4 = *(const float4*)(g_Amat + (size_t)node * HH + c);
    float4 o;
    o.x = fmaxf(a4.x + rm.x, 0.f);
    o.y = fmaxf(a4.y + rm.y, 0.f);
    o.z = fmaxf(a4.z + rm.z, 0.f);
    o.w = fmaxf(a4.w + rm.w, 0.f);
    size_t so = (size_t)node * HH + c;
    *(__half2*)(g_ag16 + so)     = __floats2half2_rn(o.x, o.y);
    *(__half2*)(g_ag16 + so + 2) = __floats2half2_rn(o.z, o.w);
}

// ============================ fused decoder y + h column sums + tau ============================
__global__ __launch_bounds__(256)
void yh_kernel(const float* __restrict__ h, const float* __restrict__ W_dec,
               const float* __restrict__ b_dec,
               const float* __restrict__ W_term, const float* __restrict__ b_term,
               float* __restrict__ y, float* __restrict__ tau) {
    int warp = threadIdx.x >> 5;
    int lane = threadIdx.x & 31;
    int c = lane * 4;
    float4 wz = *(const float4*)(W_dec + c);
    float4 wh = *(const float4*)(W_dec + HH + c);
    float bd = b_dec[0];
    float4 cs = make_float4(0.f, 0.f, 0.f, 0.f);
    for (int node = blockIdx.x * 8 + warp; node < NN; node += gridDim.x * 8) {
        float4 z4 = *(const float4*)(g_z + (size_t)node * HH + c);
        float4 h4 = *(const float4*)(h + (size_t)node * HH + c);
        cs.x += h4.x; cs.y += h4.y; cs.z += h4.z; cs.w += h4.w;
        float s = z4.x * wz.x + z4.y * wz.y + z4.z * wz.z + z4.w * wz.w
                + h4.x * wh.x + h4.y * wh.y + h4.z * wh.z + h4.w * wh.w;
#pragma unroll
        for (int o = 16; o; o >>= 1) s += __shfl_down_sync(0xFFFFFFFFu, s, o);
        if (lane == 0) y[node] = s + bd;
    }
    __shared__ float sm[8][128];
    __shared__ int isLast;
    *(float4*)&sm[warp][c] = cs;
    __syncthreads();
    if (threadIdx.x < 128) {
        int col = threadIdx.x;
        float s = 0.f;
#pragma unroll
        for (int w = 0; w < 8; w++) s += sm[w][col];
        atomicAdd(&g_hsum[col], s);
    }
    __threadfence();
    __syncthreads();
    if (threadIdx.x == 0) {
        int t = atomicAdd(&g_done, 1);
        isLast = (t == (int)gridDim.x - 1) ? 1 : 0;
    }
    __syncthreads();
    if (isLast) {
        __shared__ float red[128];
        if (threadIdx.x < 128) {
            int t = threadIdx.x;
            float hs = *((volatile float*)&g_hsum[t]);
            red[t] = hs * (1.0f / (float)NN) * (W_term[t] + W_term[t + HH]);
        }
        __syncthreads();
        for (int o = 64; o; o >>= 1) {
            if (threadIdx.x < o && threadIdx.x + o < 128) red[threadIdx.x] += red[threadIdx.x + o];
            __syncthreads();
        }
        if (threadIdx.x == 0) tau[0] = red[0] + b_term[0];
    }
}

// ============================ launch ============================
extern "C" void kernel_launch(void* const* d_in, const int* in_sizes, int n_in,
                              void* d_out, int out_size)
{
    const float* x         = (const float*)d_in[0];
    const float* pre_h     = (const float*)d_in[1];
    const int*   edge_idx  = (const int*)  d_in[2];
    const float* edge_attr = (const float*)d_in[3];
    const float* W_enc     = (const float*)d_in[4];
    const float* b_enc     = (const float*)d_in[5];
    const float* W_M       = (const float*)d_in[6];
    const float* b_M       = (const float*)d_in[7];
    const float* W_U       = (const float*)d_in[8];
    const float* b_U       = (const float*)d_in[9];
    const float* W_dec     = (const float*)d_in[10];
    const float* b_dec     = (const float*)d_in[11];
    const float* W_term    = (const float*)d_in[12];
    const float* b_term    = (const float*)d_in[13];

    float* out   = (float*)d_out;
    float* h_out = out;
    float* y_out = out + (size_t)NN * HH;
    float* tau_o = out + (size_t)NN * HH + NN;

    const int* src = edge_idx;
    const int* dst = edge_idx + EE;

    float* z_p;  cudaGetSymbolAddress((void**)&z_p,  g_z);
    float* A_p;  cudaGetSymbolAddress((void**)&A_p,  g_Amat);
    __half* B16_p; cudaGetSymbolAddress((void**)&B16_p, g_B16);
    __half *ph16, *z16, *ag16;
    cudaGetSymbolAddress((void**)&ph16, g_ph16);
    cudaGetSymbolAddress((void**)&z16,  g_z16);
    cudaGetSymbolAddress((void**)&ag16, g_ag16);
    __half *wench, *wencl, *wmsgh, *wmsgl, *wupdh, *wupdl;
    cudaGetSymbolAddress((void**)&wench, g_Wenc_h);
    cudaGetSymbolAddress((void**)&wencl, g_Wenc_l);
    cudaGetSymbolAddress((void**)&wmsgh, g_Wmsg_h);
    cudaGetSymbolAddress((void**)&wmsgl, g_Wmsg_l);
    cudaGetSymbolAddress((void**)&wupdh, g_Wupd_h);
    cudaGetSymbolAddress((void**)&wupdl, g_Wupd_l);

    cudaFuncSetAttribute(gemm_mma, cudaFuncAttributeMaxDynamicSharedMemorySize, SM_TOTAL);

    cudaStream_t s1;
    cudaStreamCreateWithFlags(&s1, cudaStreamNonBlocking);
    cudaEvent_t evA, evB;
    cudaEventCreateWithFlags(&evA, cudaEventDisableTiming);
    cudaEventCreateWithFlags(&evB, cudaEventDisableTiming);

    const int gemmGridX = (NN + 63) / 64;     // 782
    const int eBlocks   = (EE + 255) / 256;
    const int nWarpBlocks = (NN + 7) / 8;

    // 0) init — R9 topology
    init_kernel<<<(NN + 255) / 256, 256>>>();
    cudaEventRecord(evA, 0);

    // ---- branch s1: CSR build ----
    cudaStreamWaitEvent(s1, evA, 0);
    hist_kernel<<<eBlocks, 256, 0, s1>>>(dst);
    scan_kernel<<<1, 1024, 0, s1>>>();
    scatter_kernel<<<eBlocks, 256, 0, s1>>>(src, dst, edge_attr);
    cudaEventRecord(evB, s1);

    // ---- main chain: prep ----
    prep_w_kernel<<<320, 256>>>(W_enc, W_M, W_U);
    prep_x_kernel<<<(NN * 64 + 255) / 256, 256>>>(pre_h, ph16, NN * 64);

    // encoder: grid (782,1), NB=2; writes fp32 z (for yh) + fp16 z (for GEMMs)
    gemm_mma<<<dim3(gemmGridX, 1), 256, SM_TOTAL>>>(
        ph16, nullptr, 1, wench, wencl, 128, 2,
        b_enc, nullptr, x, W_enc,
        z_p, nullptr, nullptr, z16, NN, 1);

    // fused msg: grid (782,2), NB=2; A fp32, B fp16
    gemm_mma<<<dim3(gemmGridX, 2), 256, SM_TOTAL>>>(
        z16, nullptr, 1, wmsgh, wmsgl, 128, 2,
        b_M, nullptr, nullptr, nullptr,
        A_p, nullptr, B16_p, nullptr, NN, 0);

    // ---- join CSR, aggregate ----
    cudaStreamWaitEvent(0, evB, 0);
    agg_kernel<<<nWarpBlocks, 256>>>(W_M);

    // update: grid (782,2), NB=1, K=2 chunks (z16 + ag16)
    gemm_mma<<<dim3(gemmGridX, 2), 256, SM_TOTAL>>>(
        z16, ag16, 2, wupdh, wupdl, 256, 1,
        b_U, nullptr, nullptr, nullptr,
        h_out, nullptr, nullptr, nullptr, NN, 1);

    // ---- fused decoder + column sums + tau ----
    yh_kernel<<<384, 256>>>(h_out, W_dec, b_dec, W_term, b_term, y_out, tau_o);
}